// round 10
// baseline (speedup 1.0000x reference)
#include <cuda_runtime.h>
#include <cuda_bf16.h>
#include <cstdint>
#include <math.h>

// Problem constants
#define TT 4
#define BB 8
#define CC 256
#define NN 256
#define TNTOK 1024   // T*N
#define NH 8
#define DHD 32

// ---------------------------------------------------------------------------
// Scratch (device globals; no allocation allowed)
// ---------------------------------------------------------------------------
__device__ __align__(16) float    g_qkv [BB * 768 * TNTOK];
__device__ __align__(16) float    g_proj[BB * CC * TNTOK];
__device__ __align__(16) float    g_oat [BB * NH * TNTOK * DHD];
__device__ __align__(16) unsigned g_qw  [BB * NH * TNTOK];
__device__ __align__(16) unsigned g_kw  [BB * NH * TNTOK];
__device__ __align__(16) unsigned g_vw  [BB * NH * TNTOK];
__device__ __align__(16) float    g_scale[1024];
// weight splits (3-term bf16)
__device__ __align__(16) __nv_bfloat16 g_ws[3 * 768 * 256];   // qkv weight splits
__device__ __align__(16) __nv_bfloat16 g_wp[3 * 256 * 256];   // proj weight splits
// X splits for qkv GEMM: [s][b][l][c] bf16
__device__ __align__(16) __nv_bfloat16 g_xs[3 * BB * TNTOK * CC];
// transposed bf16 spikes for proj GEMM: [b][l][c]
__device__ __align__(16) __nv_bfloat16 g_s2t[BB * TNTOK * CC];
// attention-restructure buffers
__device__ __align__(16) __nv_bfloat16 g_bs[NH * 2 * 4 * 256 * 256]; // [h][split][dt][ni][nj]
__device__ __align__(16) __nv_bfloat16 g_vt[NH * 4 * 256 * 256];     // [h][tj][col=b*32+d][nj]
__device__ __align__(16) float         g_t2[NH * 4 * 256 * 256];     // [h][ti][ni][col]

// ---------------------------------------------------------------------------
// Helpers
// ---------------------------------------------------------------------------
__device__ __forceinline__ uint32_t s2u(const void* p) {
    uint32_t a;
    asm("{ .reg .u64 t; cvta.to.shared.u64 t, %1; cvt.u32.u64 %0, t; }" : "=r"(a) : "l"(p));
    return a;
}
__device__ __forceinline__ void cpasync16(uint32_t dst, const void* src) {
    asm volatile("cp.async.cg.shared.global [%0], [%1], 16;" :: "r"(dst), "l"(src));
}
__device__ __forceinline__ void ldsm_x4(uint32_t& r0, uint32_t& r1, uint32_t& r2, uint32_t& r3,
                                        uint32_t addr) {
    asm volatile("ldmatrix.sync.aligned.m8n8.x4.shared.b16 {%0,%1,%2,%3}, [%4];"
                 : "=r"(r0), "=r"(r1), "=r"(r2), "=r"(r3) : "r"(addr));
}
__device__ __forceinline__ void mma_bf16(float& c0, float& c1, float& c2, float& c3,
                                         uint32_t a0, uint32_t a1, uint32_t a2, uint32_t a3,
                                         uint32_t b0, uint32_t b1) {
    asm volatile("mma.sync.aligned.m16n8k16.row.col.f32.bf16.bf16.f32 "
                 "{%0,%1,%2,%3}, {%4,%5,%6,%7}, {%8,%9}, {%0,%1,%2,%3};"
                 : "+f"(c0), "+f"(c1), "+f"(c2), "+f"(c3)
                 : "r"(a0), "r"(a1), "r"(a2), "r"(a3), "r"(b0), "r"(b1));
}

// LIF step
__device__ __forceinline__ float lif_step(float& mem, float sp, float x) {
    mem = (mem - 0.5f * sp) * 0.25f + x;
    return rintf(fminf(fmaxf(mem, 0.0f), 1.0f));
}

// ---------------------------------------------------------------------------
// Prep: BN scales
// ---------------------------------------------------------------------------
__global__ void prep_kernel(const float* __restrict__ qg, const float* __restrict__ qv,
                            const float* __restrict__ pg, const float* __restrict__ pv) {
    int o = threadIdx.x;
    if (o < 768) {
        float vv = qv[o] + 1e-5f;
        g_scale[o] = qg[o] * (float)(1.0 / sqrt((double)vv));
    }
    if (o < 256) {
        float vv = pv[o] + 1e-5f;
        g_scale[768 + o] = pg[o] * (float)(1.0 / sqrt((double)vv));
    }
}

// ---------------------------------------------------------------------------
// Split weights into 3 bf16 terms (hi, lo, ll)
// ---------------------------------------------------------------------------
__global__ void __launch_bounds__(256) split_w(const float* __restrict__ wq,
                                               const float* __restrict__ wp) {
    int i = blockIdx.x * 256 + threadIdx.x;
    float v;
    __nv_bfloat16* base;
    int stride, idx;
    if (i < 196608) { v = wq[i]; base = g_ws; stride = 196608; idx = i; }
    else            { idx = i - 196608; v = wp[idx]; base = g_wp; stride = 65536; }
    __nv_bfloat16 h = __float2bfloat16(v);
    float r1 = v - __bfloat162float(h);
    __nv_bfloat16 l = __float2bfloat16(r1);
    float r2 = r1 - __bfloat162float(l);
    base[idx]              = h;
    base[stride + idx]     = l;
    base[2 * stride + idx] = __float2bfloat16(r2);
}

// ---------------------------------------------------------------------------
// X convert: X[b][c][l] fp32 -> g_xs[s][b][l][c] bf16 (3 splits, transposed)
// ---------------------------------------------------------------------------
__global__ void __launch_bounds__(256) x_convert(const float* __restrict__ X) {
    __shared__ float st[32][33];
    int l0 = blockIdx.x * 32;
    int c0 = blockIdx.y * 32;
    int b  = blockIdx.z;
    int tid = threadIdx.x;
    const float* Xb = X + (size_t)b * (CC * TNTOK);
#pragma unroll
    for (int r = 0; r < 4; r++) {
        int idx = r * 256 + tid;
        int cl = idx >> 5, ll = idx & 31;
        st[cl][ll] = Xb[(size_t)(c0 + cl) * TNTOK + l0 + ll];
    }
    __syncthreads();
#pragma unroll
    for (int r = 0; r < 4; r++) {
        int idx = r * 256 + tid;
        int ll = idx >> 5, cl = idx & 31;
        float v = st[cl][ll];
        __nv_bfloat16 h = __float2bfloat16(v);
        float r1 = v - __bfloat162float(h);
        __nv_bfloat16 l = __float2bfloat16(r1);
        float r2 = r1 - __bfloat162float(l);
        size_t base = ((size_t)b * TNTOK + l0 + ll) * CC + c0 + cl;
        const size_t SS = (size_t)BB * TNTOK * CC;
        g_xs[base]          = h;
        g_xs[base + SS]     = l;
        g_xs[base + 2 * SS] = __float2bfloat16(r2);
    }
}

// ---------------------------------------------------------------------------
// QKV GEMM, double-buffered across k-steps. Per k-step: 3 A splits + 3 B
// splits via cp.async (48 KB) into stage p; compute 192 MMAs/warp from stage
// 1-p under the in-flight load. Dynamic SMEM: 2 x 61440 = 122880 B; 1 CTA/SM.
// grid (8 l-tiles, 6 m-tiles, 8 b), 256 threads = 8 warps (2M x 4N).
// ---------------------------------------------------------------------------
__global__ void __launch_bounds__(256) qkv_gemm(const float* __restrict__ meanv,
                                                const float* __restrict__ betav) {
    extern __shared__ __align__(16) char dyn[];

    int tid = threadIdx.x;
    int wid = tid >> 5, lane = tid & 31;
    int l0 = blockIdx.x * 128;
    int m0 = blockIdx.y * 128;
    int b  = blockIdx.z;
    int wm = wid >> 2, wn = wid & 3;

    const size_t SS = (size_t)BB * TNTOK * CC;

    float acc[4][4][4];
#pragma unroll
    for (int mt = 0; mt < 4; mt++)
#pragma unroll
        for (int nt = 0; nt < 4; nt++)
#pragma unroll
            for (int q = 0; q < 4; q++) acc[mt][nt][q] = 0.0f;

    auto stA = [&](int p) { return (__nv_bfloat16*)(dyn + p * 61440); };           // [3][128][40]
    auto stB = [&](int p) { return (__nv_bfloat16*)(dyn + p * 61440 + 30720); };   // [3][128][40]

    auto load_step = [&](int ks, int p) {
        int k0 = ks * 32;
        __nv_bfloat16* dA = stA(p);
        __nv_bfloat16* dB = stB(p);
#pragma unroll
        for (int r = 0; r < 6; r++) {
            int idx = tid + r * 256;
            int s = idx >> 9, rem = idx & 511;
            int row = rem >> 2, c16 = rem & 3;
            const __nv_bfloat16* srcA =
                g_ws + (size_t)s * 196608 + (size_t)(m0 + row) * 256 + k0 + c16 * 8;
            cpasync16(s2u(dA + ((s * 128 + row) * 40 + c16 * 8)), srcA);
            const __nv_bfloat16* srcB =
                g_xs + (size_t)s * SS + ((size_t)b * TNTOK + l0 + row) * CC + k0 + c16 * 8;
            cpasync16(s2u(dB + ((s * 128 + row) * 40 + c16 * 8)), srcB);
        }
        asm volatile("cp.async.commit_group;" ::: "memory");
    };

    load_step(0, 0);

    for (int ks = 0; ks < 8; ++ks) {
        int p = ks & 1;
        if (ks + 1 < 8) {
            load_step(ks + 1, 1 - p);
            asm volatile("cp.async.wait_group 1;" ::: "memory");
        } else {
            asm volatile("cp.async.wait_group 0;" ::: "memory");
        }
        __syncthreads();

        __nv_bfloat16* sA = stA(p);
        __nv_bfloat16* sB = stB(p);
#pragma unroll
        for (int k16 = 0; k16 < 2; k16++) {
            int kk0 = k16 * 16;
#pragma unroll
            for (int sa = 0; sa < 3; sa++) {
                uint32_t af[4][4];
#pragma unroll
                for (int mt = 0; mt < 4; mt++) {
                    int mrow = wm * 64 + mt * 16 + (lane & 15);
                    int kk = kk0 + ((lane >> 4) << 3);
                    ldsm_x4(af[mt][0], af[mt][1], af[mt][2], af[mt][3],
                            s2u(sA + ((sa * 128 + mrow) * 40 + kk)));
                }
                int nsb = (sa == 0) ? 3 : ((sa == 1) ? 2 : 1);
#pragma unroll
                for (int sb = 0; sb < 3; sb++) {
                    if (sb >= nsb) break;
                    uint32_t bfr[2][4];
#pragma unroll
                    for (int np = 0; np < 2; np++) {
                        int nrow = wn * 32 + np * 16 + (lane & 7) + ((lane >> 4) << 3);
                        int kk = kk0 + (((lane >> 3) & 1) << 3);
                        ldsm_x4(bfr[np][0], bfr[np][1], bfr[np][2], bfr[np][3],
                                s2u(sB + ((sb * 128 + nrow) * 40 + kk)));
                    }
#pragma unroll
                    for (int mt = 0; mt < 4; mt++)
#pragma unroll
                        for (int nt = 0; nt < 4; nt++) {
                            uint32_t b0 = bfr[nt >> 1][(nt & 1) * 2];
                            uint32_t b1 = bfr[nt >> 1][(nt & 1) * 2 + 1];
                            mma_bf16(acc[mt][nt][0], acc[mt][nt][1],
                                     acc[mt][nt][2], acc[mt][nt][3],
                                     af[mt][0], af[mt][1], af[mt][2], af[mt][3], b0, b1);
                        }
                }
            }
        }
        __syncthreads();
    }

    // BN epilogue + store to g_qkv[b][m][l]
    float* Cb = g_qkv + (size_t)b * (768 * TNTOK);
#pragma unroll
    for (int mt = 0; mt < 4; mt++) {
        int row0 = m0 + wm * 64 + mt * 16 + (lane >> 2);
        int row1 = row0 + 8;
        float sc0 = g_scale[row0], mu0 = meanv[row0], be0 = betav[row0];
        float sc1 = g_scale[row1], mu1 = meanv[row1], be1 = betav[row1];
#pragma unroll
        for (int nt = 0; nt < 4; nt++) {
            int col = l0 + wn * 32 + nt * 8 + ((lane & 3) << 1);
            float2 lo2, hi2;
            lo2.x = (acc[mt][nt][0] - mu0) * sc0 + be0;
            lo2.y = (acc[mt][nt][1] - mu0) * sc0 + be0;
            hi2.x = (acc[mt][nt][2] - mu1) * sc1 + be1;
            hi2.y = (acc[mt][nt][3] - mu1) * sc1 + be1;
            *(float2*)(Cb + (size_t)row0 * TNTOK + col) = lo2;
            *(float2*)(Cb + (size_t)row1 * TNTOK + col) = hi2;
        }
    }
}

// ---------------------------------------------------------------------------
// Proj GEMM: C[b,o,l] = sum_c Wp[o,c]*s2[c,l] (+ b_proj, BN). Spikes exact bf16.
// ---------------------------------------------------------------------------
__global__ void __launch_bounds__(256) proj_gemm(const float* __restrict__ meanv,
                                                 const float* __restrict__ betav,
                                                 const float* __restrict__ addb) {
    __shared__ __align__(16) __nv_bfloat16 sA[3][128][40];
    __shared__ __align__(16) __nv_bfloat16 sB[128][40];

    int tid = threadIdx.x;
    int wid = tid >> 5, lane = tid & 31;
    int l0 = blockIdx.x * 128;
    int m0 = blockIdx.y * 128;
    int b  = blockIdx.z;
    int wm = wid >> 2, wn = wid & 3;

    float acc[4][4][4];
#pragma unroll
    for (int mt = 0; mt < 4; mt++)
#pragma unroll
        for (int nt = 0; nt < 4; nt++)
#pragma unroll
            for (int q = 0; q < 4; q++) acc[mt][nt][q] = 0.0f;

    for (int k0 = 0; k0 < 256; k0 += 32) {
#pragma unroll
        for (int r = 0; r < 6; r++) {
            int idx = tid + r * 256;
            int s = idx >> 9, rem = idx & 511;
            int row = rem >> 2, c16 = rem & 3;
            const __nv_bfloat16* src =
                g_wp + (size_t)s * 65536 + (size_t)(m0 + row) * 256 + k0 + c16 * 8;
            cpasync16(s2u(&sA[s][row][c16 * 8]), src);
        }
#pragma unroll
        for (int r = 0; r < 2; r++) {
            int idx = tid + r * 256;
            int row = idx >> 2, c16 = idx & 3;
            const __nv_bfloat16* src =
                g_s2t + ((size_t)b * TNTOK + l0 + row) * CC + k0 + c16 * 8;
            cpasync16(s2u(&sB[row][c16 * 8]), src);
        }
        asm volatile("cp.async.commit_group;" ::: "memory");
        asm volatile("cp.async.wait_group 0;" ::: "memory");
        __syncthreads();

#pragma unroll
        for (int k16 = 0; k16 < 2; k16++) {
            int kk0 = k16 * 16;
            uint32_t bfr[2][4];
#pragma unroll
            for (int np = 0; np < 2; np++) {
                int nrow = wn * 32 + np * 16 + (lane & 7) + ((lane >> 4) << 3);
                int kk = kk0 + (((lane >> 3) & 1) << 3);
                ldsm_x4(bfr[np][0], bfr[np][1], bfr[np][2], bfr[np][3],
                        s2u(&sB[nrow][kk]));
            }
#pragma unroll
            for (int sa = 0; sa < 3; sa++) {
                uint32_t af[4][4];
#pragma unroll
                for (int mt = 0; mt < 4; mt++) {
                    int mrow = wm * 64 + mt * 16 + (lane & 15);
                    int kk = kk0 + ((lane >> 4) << 3);
                    ldsm_x4(af[mt][0], af[mt][1], af[mt][2], af[mt][3],
                            s2u(&sA[sa][mrow][kk]));
                }
#pragma unroll
                for (int mt = 0; mt < 4; mt++)
#pragma unroll
                    for (int nt = 0; nt < 4; nt++) {
                        uint32_t b0 = bfr[nt >> 1][(nt & 1) * 2];
                        uint32_t b1 = bfr[nt >> 1][(nt & 1) * 2 + 1];
                        mma_bf16(acc[mt][nt][0], acc[mt][nt][1],
                                 acc[mt][nt][2], acc[mt][nt][3],
                                 af[mt][0], af[mt][1], af[mt][2], af[mt][3], b0, b1);
                    }
            }
        }
        __syncthreads();
    }

    float* Cb = g_proj + (size_t)b * (CC * TNTOK);
#pragma unroll
    for (int mt = 0; mt < 4; mt++) {
        int row0 = m0 + wm * 64 + mt * 16 + (lane >> 2);
        int row1 = row0 + 8;
        float sc0 = g_scale[768 + row0], mu0 = meanv[row0], be0 = betav[row0], ab0 = addb[row0];
        float sc1 = g_scale[768 + row1], mu1 = meanv[row1], be1 = betav[row1], ab1 = addb[row1];
#pragma unroll
        for (int nt = 0; nt < 4; nt++) {
            int col = l0 + wn * 32 + nt * 8 + ((lane & 3) << 1);
            float2 lo2, hi2;
            lo2.x = (acc[mt][nt][0] + ab0 - mu0) * sc0 + be0;
            lo2.y = (acc[mt][nt][1] + ab0 - mu0) * sc0 + be0;
            hi2.x = (acc[mt][nt][2] + ab1 - mu1) * sc1 + be1;
            hi2.y = (acc[mt][nt][3] + ab1 - mu1) * sc1 + be1;
            *(float2*)(Cb + (size_t)row0 * TNTOK + col) = lo2;
            *(float2*)(Cb + (size_t)row1 * TNTOK + col) = hi2;
        }
    }
}

// ---------------------------------------------------------------------------
// LIF1 + bit-pack
// ---------------------------------------------------------------------------
__global__ void __launch_bounds__(256) lif1_kernel() {
    int g = blockIdx.x;
    int b = blockIdx.y;
    int n = threadIdx.x;
    const float* src = g_qkv + ((size_t)(b * 768 + g * 32)) * TNTOK + n;
    unsigned w0 = 0, w1 = 0, w2 = 0, w3 = 0;
#pragma unroll
    for (int d = 0; d < 32; d++) {
        const float* p = src + (size_t)d * TNTOK;
        float mem = 0.0f, sp = 0.0f;
        float s;
        s = lif_step(mem, sp, p[0]);   w0 |= ((unsigned)s) << d; sp = s;
        s = lif_step(mem, sp, p[256]); w1 |= ((unsigned)s) << d; sp = s;
        s = lif_step(mem, sp, p[512]); w2 |= ((unsigned)s) << d; sp = s;
        s = lif_step(mem, sp, p[768]); w3 |= ((unsigned)s) << d;
    }
    int which = g >> 3, h = g & 7;
    unsigned* dst = (which == 0) ? g_qw : ((which == 1) ? g_kw : g_vw);
    size_t base = (size_t)(b * NH + h) * TNTOK + n;
    dst[base]       = w0;
    dst[base + 256] = w1;
    dst[base + 512] = w2;
    dst[base + 768] = w3;
}

// ---------------------------------------------------------------------------
// Build bias block-Toeplitz matrices (bf16 hi/lo)
// ---------------------------------------------------------------------------
__global__ void __launch_bounds__(256) build_bias(const float* __restrict__ bias_table) {
    int ni = blockIdx.x;
    int by = blockIdx.y;
    int h = by >> 2, dt = by & 3;
    int nj = threadIdx.x;
    int yi = ni >> 4, xi = ni & 15;
    int yj = nj >> 4, xj = nj & 15;
    int idx = (dt + 3) * 961 + (yi - yj + 15) * 31 + (xi - xj + 15);
    float f = bias_table[idx * NH + h];
    __nv_bfloat16 hi = __float2bfloat16(f);
    __nv_bfloat16 lo = __float2bfloat16(f - __bfloat162float(hi));
    size_t b0 = ((size_t)(((h * 2 + 0) * 4 + dt) * 256 + ni)) * 256 + nj;
    size_t b1 = ((size_t)(((h * 2 + 1) * 4 + dt) * 256 + ni)) * 256 + nj;
    g_bs[b0] = hi;
    g_bs[b1] = lo;
}

// ---------------------------------------------------------------------------
// Build V^T as bf16 {0,1}
// ---------------------------------------------------------------------------
__global__ void __launch_bounds__(256) build_vt() {
    int col = blockIdx.x;
    int by = blockIdx.y;
    int h = by >> 2, tj = by & 3;
    int nj = threadIdx.x;
    int b = col >> 5, d = col & 31;
    unsigned w = g_vw[(size_t)(b * NH + h) * TNTOK + tj * 256 + nj];
    g_vt[((size_t)((h * 4 + tj) * 256 + col)) * 256 + nj] =
        ((w >> d) & 1u) ? __float2bfloat16(1.0f) : __float2bfloat16(0.0f);
}

// ---------------------------------------------------------------------------
// term2 GEMM via mma.sync, 4-stage pipelined (validated R8)
// ---------------------------------------------------------------------------
__global__ void __launch_bounds__(256) term2_gemm() {
    extern __shared__ __align__(16) char t2s[];

    int tid = threadIdx.x;
    int wid = tid >> 5, lane = tid & 31;
    int bx = blockIdx.x;            // ((h*4+ti)*2+mh)*2+nh2
    int nh2 = bx & 1, mh = (bx >> 1) & 1, ti = (bx >> 2) & 3, h = bx >> 4;

    int wm = wid >> 2, wn = wid & 3;
    const int half = (ti + 1) * 8;
    const int niter = half * 2;

    float acc[4][4][4];
#pragma unroll
    for (int mt = 0; mt < 4; mt++)
#pragma unroll
        for (int nt = 0; nt < 4; nt++)
#pragma unroll
            for (int q = 0; q < 4; q++) acc[mt][nt][q] = 0.0f;

    auto tileA = [&](int st) { return (__nv_bfloat16*)(t2s + st * 20480); };
    auto tileB = [&](int st) { return (__nv_bfloat16*)(t2s + st * 20480 + 10240); };

    auto load_chunk = [&](int it, int p) {
        int s = (it >= half) ? 1 : 0;
        int rem = it - s * half;
        int tj = rem >> 3, kc = rem & 7, dt = ti - tj;
        const __nv_bfloat16* Asrc =
            g_bs + ((size_t)(((h * 2 + s) * 4 + dt) * 256 + mh * 128)) * 256 + kc * 32;
        const __nv_bfloat16* Bsrc =
            g_vt + ((size_t)((h * 4 + tj) * 256 + nh2 * 128)) * 256 + kc * 32;
        __nv_bfloat16* dA = tileA(p);
        __nv_bfloat16* dB = tileB(p);
#pragma unroll
        for (int r = 0; r < 2; r++) {
            int ix = tid + r * 256;
            int row = ix >> 2, c16 = ix & 3;
            cpasync16(s2u(dA + row * 40 + c16 * 8), Asrc + (size_t)row * 256 + c16 * 8);
            cpasync16(s2u(dB + row * 40 + c16 * 8), Bsrc + (size_t)row * 256 + c16 * 8);
        }
        asm volatile("cp.async.commit_group;" ::: "memory");
    };

    load_chunk(0, 0);
    load_chunk(1, 1);
    load_chunk(2, 2);

    for (int it = 0; it < niter; ++it) {
        int p = it & 3;
        if (it + 3 < niter) {
            load_chunk(it + 3, (it + 3) & 3);
            asm volatile("cp.async.wait_group 3;" ::: "memory");
        } else {
            int rem = niter - 1 - it;
            if (rem == 2)      asm volatile("cp.async.wait_group 2;" ::: "memory");
            else if (rem == 1) asm volatile("cp.async.wait_group 1;" ::: "memory");
            else               asm volatile("cp.async.wait_group 0;" ::: "memory");
        }
        __syncthreads();

        __nv_bfloat16* cA = tileA(p);
        __nv_bfloat16* cB = tileB(p);
#pragma unroll
        for (int k16 = 0; k16 < 2; k16++) {
            int k0 = k16 * 16;
            uint32_t af[4][4];
#pragma unroll
            for (int mt = 0; mt < 4; mt++) {
                int mrow = wm * 64 + mt * 16 + (lane & 15);
                int kk = k0 + ((lane >> 4) << 3);
                ldsm_x4(af[mt][0], af[mt][1], af[mt][2], af[mt][3],
                        s2u(cA + mrow * 40 + kk));
            }
            uint32_t bfr[2][4];
#pragma unroll
            for (int np = 0; np < 2; np++) {
                int nrow = wn * 32 + np * 16 + (lane & 7) + ((lane >> 4) << 3);
                int kk = k0 + (((lane >> 3) & 1) << 3);
                ldsm_x4(bfr[np][0], bfr[np][1], bfr[np][2], bfr[np][3],
                        s2u(cB + nrow * 40 + kk));
            }
#pragma unroll
            for (int mt = 0; mt < 4; mt++)
#pragma unroll
                for (int nt = 0; nt < 4; nt++) {
                    uint32_t b0 = bfr[nt >> 1][(nt & 1) * 2];
                    uint32_t b1 = bfr[nt >> 1][(nt & 1) * 2 + 1];
                    mma_bf16(acc[mt][nt][0], acc[mt][nt][1], acc[mt][nt][2], acc[mt][nt][3],
                             af[mt][0], af[mt][1], af[mt][2], af[mt][3], b0, b1);
                }
        }
        __syncthreads();
    }

#pragma unroll
    for (int mt = 0; mt < 4; mt++) {
#pragma unroll
        for (int nt = 0; nt < 4; nt++) {
            int row = mh * 128 + wm * 64 + mt * 16 + (lane >> 2);
            int col = nh2 * 128 + wn * 32 + nt * 8 + ((lane & 3) << 1);
            float* pD = g_t2 + ((size_t)((h * 4 + ti) * 256 + row)) * 256 + col;
            float2 lo2 = make_float2(acc[mt][nt][0], acc[mt][nt][1]);
            float2 hi2 = make_float2(acc[mt][nt][2], acc[mt][nt][3]);
            *(float2*)pD = lo2;
            *(float2*)(pD + 8 * 256) = hi2;
        }
    }
}

// ---------------------------------------------------------------------------
// Combine: term1 (exact popc prefix matrix) + term2
// ---------------------------------------------------------------------------
__global__ void __launch_bounds__(256) combine_kernel() {
    __shared__ unsigned sKt[32][32];
    __shared__ unsigned sVt[32][32];
    __shared__ __align__(16) float sM[32][32];

    int ti = blockIdx.x;
    int bh = blockIdx.y;
    int b = bh >> 3, h = bh & 7;
    int tid = threadIdx.x;
    int wid = tid >> 5, ln = tid & 31;
    int nwords = 8 * (ti + 1);

    for (int jg = wid; jg < nwords; jg += 8) {
        unsigned kwv = g_kw[(size_t)bh * TNTOK + jg * 32 + ln];
        unsigned vwv = g_vw[(size_t)bh * TNTOK + jg * 32 + ln];
#pragma unroll
        for (int c = 0; c < 32; c++) {
            unsigned bk = __ballot_sync(0xffffffffu, (kwv >> c) & 1u);
            unsigned bv = __ballot_sync(0xffffffffu, (vwv >> c) & 1u);
            if (ln == c) { sKt[c][jg] = bk; sVt[c][jg] = bv; }
        }
    }
    __syncthreads();

    {
        int c = tid >> 3;
        int d0 = (tid & 7) * 4;
#pragma unroll
        for (int u = 0; u < 4; u++) {
            int d = d0 + u;
            int sum = 0;
            for (int w = 0; w < nwords; w++) sum += __popc(sKt[c][w] & sVt[d][w]);
            sM[c][d] = (float)sum;
        }
    }
    __syncthreads();

    int n = tid;
    unsigned qw = g_qw[(size_t)bh * TNTOK + ti * 256 + n];
    float acc[32];
#pragma unroll
    for (int d = 0; d < 32; d++) acc[d] = 0.0f;
#pragma unroll
    for (int c = 0; c < 32; c++) {
        if ((qw >> c) & 1u) {
#pragma unroll
            for (int q = 0; q < 8; q++) {
                float4 m4 = *(const float4*)&sM[c][q * 4];
                acc[q * 4 + 0] += m4.x;
                acc[q * 4 + 1] += m4.y;
                acc[q * 4 + 2] += m4.z;
                acc[q * 4 + 3] += m4.w;
            }
        }
    }
    const float* t2 = g_t2 + ((size_t)((h * 4 + ti) * 256 + n)) * 256 + b * 32;
    float* outp = g_oat + ((size_t)bh * TNTOK + ti * 256 + n) * DHD;
#pragma unroll
    for (int q = 0; q < 8; q++) {
        float4 t = *(const float4*)(t2 + q * 4);
        float4 o;
        o.x = 0.125f * (acc[q * 4 + 0] + t.x);
        o.y = 0.125f * (acc[q * 4 + 1] + t.y);
        o.z = 0.125f * (acc[q * 4 + 2] + t.z);
        o.w = 0.125f * (acc[q * 4 + 3] + t.w);
        *(float4*)(outp + q * 4) = o;
    }
}

// ---------------------------------------------------------------------------
// LIF2: attention output -> transposed bf16 spikes g_s2t[b][l][c]
// ---------------------------------------------------------------------------
__global__ void __launch_bounds__(256) lif2_kernel() {
    int bh = blockIdx.x;
    int b = bh >> 3, h = bh & 7;
    int tid = threadIdx.x;
    int w = tid >> 5, lane = tid & 31;
    for (int j = 0; j < 32; j++) {
        int n = w * 32 + j;
        const float* base = g_oat + ((size_t)bh * TNTOK + n) * DHD + lane;
        float x0 = base[0];
        float x1 = base[256 * DHD];
        float x2 = base[512 * DHD];
        float x3 = base[768 * DHD];
        float mem = 0.0f, sp = 0.0f;
        float s0 = lif_step(mem, sp, x0); sp = s0;
        float s1 = lif_step(mem, sp, x1); sp = s1;
        float s2v = lif_step(mem, sp, x2); sp = s2v;
        float s3 = lif_step(mem, sp, x3);
        size_t o = ((size_t)b * TNTOK + n) * CC + h * DHD + lane;
        g_s2t[o]            = __float2bfloat16(s0);
        g_s2t[o + 256 * CC] = __float2bfloat16(s1);
        g_s2t[o + 512 * CC] = __float2bfloat16(s2v);
        g_s2t[o + 768 * CC] = __float2bfloat16(s3);
    }
}

// ---------------------------------------------------------------------------
// LIF3: proj output -> final spikes
// ---------------------------------------------------------------------------
__global__ void __launch_bounds__(256) lif3_kernel(float* __restrict__ out) {
    int gid = blockIdx.x * 256 + threadIdx.x;
    const float* p = g_proj + (size_t)(gid >> 8) * TNTOK + (gid & 255);
    float x0 = p[0], x1 = p[256], x2 = p[512], x3 = p[768];
    float mem = 0.0f, sp = 0.0f;
    float s0 = lif_step(mem, sp, x0); sp = s0;
    float s1 = lif_step(mem, sp, x1); sp = s1;
    float s2v = lif_step(mem, sp, x2); sp = s2v;
    float s3 = lif_step(mem, sp, x3);
    out[gid]           = s0;
    out[gid +  524288] = s1;
    out[gid + 1048576] = s2v;
    out[gid + 1572864] = s3;
}

// ---------------------------------------------------------------------------
// Launch
// ---------------------------------------------------------------------------
extern "C" void kernel_launch(void* const* d_in, const int* in_sizes, int n_in,
                              void* d_out, int out_size) {
    const float* x          = (const float*)d_in[0];
    const float* w_qkv      = (const float*)d_in[1];
    const float* qkv_gamma  = (const float*)d_in[2];
    const float* qkv_beta   = (const float*)d_in[3];
    const float* qkv_mean   = (const float*)d_in[4];
    const float* qkv_var    = (const float*)d_in[5];
    const float* bias_table = (const float*)d_in[6];
    const float* w_proj     = (const float*)d_in[7];
    const float* b_proj     = (const float*)d_in[8];
    const float* proj_gamma = (const float*)d_in[9];
    const float* proj_beta  = (const float*)d_in[10];
    const float* proj_mean  = (const float*)d_in[11];
    const float* proj_var   = (const float*)d_in[12];
    float* out = (float*)d_out;

    cudaFuncSetAttribute(qkv_gemm, cudaFuncAttributeMaxDynamicSharedMemorySize, 122880);
    cudaFuncSetAttribute(term2_gemm, cudaFuncAttributeMaxDynamicSharedMemorySize, 81920);

    prep_kernel<<<1, 1024>>>(qkv_gamma, qkv_var, proj_gamma, proj_var);
    split_w<<<1024, 256>>>(w_qkv, w_proj);
    x_convert<<<dim3(32, 8, 8), 256>>>(x);
    build_bias<<<dim3(256, 32), 256>>>(bias_table);

    qkv_gemm<<<dim3(8, 6, 8), 256, 122880>>>(qkv_mean, qkv_beta);
    lif1_kernel<<<dim3(24, 8), 256>>>();

    build_vt<<<dim3(256, 32), 256>>>();
    term2_gemm<<<128, 256, 81920>>>();
    combine_kernel<<<dim3(4, 64), 256>>>();

    lif2_kernel<<<64, 256>>>();
    proj_gemm<<<dim3(8, 2, 8), 256>>>(proj_mean, proj_beta, b_proj);
    lif3_kernel<<<2048, 256>>>(out);
}

// round 12
// speedup vs baseline: 1.0825x; 1.0825x over previous
#include <cuda_runtime.h>
#include <cuda_bf16.h>
#include <cstdint>
#include <math.h>

// Problem constants
#define TT 4
#define BB 8
#define CC 256
#define NN 256
#define TNTOK 1024   // T*N
#define NH 8
#define DHD 32

// ---------------------------------------------------------------------------
// Scratch (device globals; no allocation allowed)
// ---------------------------------------------------------------------------
__device__ __align__(16) float    g_qkv [BB * 768 * TNTOK];
__device__ __align__(16) float    g_proj[BB * CC * TNTOK];
__device__ __align__(16) float    g_oat [BB * NH * TNTOK * DHD];
__device__ __align__(16) unsigned g_qw  [BB * NH * TNTOK];
__device__ __align__(16) unsigned g_kw  [BB * NH * TNTOK];
__device__ __align__(16) unsigned g_vw  [BB * NH * TNTOK];
__device__ __align__(16) float    g_scale[1024];
// weight splits (3-term bf16)
__device__ __align__(16) __nv_bfloat16 g_ws[3 * 768 * 256];   // qkv weight splits
__device__ __align__(16) __nv_bfloat16 g_wp[3 * 256 * 256];   // proj weight splits
// transposed bf16 spikes for proj GEMM: [b][l][c]
__device__ __align__(16) __nv_bfloat16 g_s2t[BB * TNTOK * CC];
// attention-restructure buffers
__device__ __align__(16) __nv_bfloat16 g_bs[NH * 2 * 4 * 256 * 256]; // [h][split][dt][ni][nj]
__device__ __align__(16) __nv_bfloat16 g_vt[NH * 4 * 256 * 256];     // [h][tj][col=b*32+d][nj]
__device__ __align__(16) float         g_t2[NH * 4 * 256 * 256];     // [h][ti][ni][col]

// ---------------------------------------------------------------------------
// Helpers
// ---------------------------------------------------------------------------
__device__ __forceinline__ uint32_t s2u(const void* p) {
    uint32_t a;
    asm("{ .reg .u64 t; cvta.to.shared.u64 t, %1; cvt.u32.u64 %0, t; }" : "=r"(a) : "l"(p));
    return a;
}
__device__ __forceinline__ void cpasync16(uint32_t dst, const void* src) {
    asm volatile("cp.async.cg.shared.global [%0], [%1], 16;" :: "r"(dst), "l"(src));
}
__device__ __forceinline__ void ldsm_x4(uint32_t& r0, uint32_t& r1, uint32_t& r2, uint32_t& r3,
                                        uint32_t addr) {
    asm volatile("ldmatrix.sync.aligned.m8n8.x4.shared.b16 {%0,%1,%2,%3}, [%4];"
                 : "=r"(r0), "=r"(r1), "=r"(r2), "=r"(r3) : "r"(addr));
}
__device__ __forceinline__ void mma_bf16(float& c0, float& c1, float& c2, float& c3,
                                         uint32_t a0, uint32_t a1, uint32_t a2, uint32_t a3,
                                         uint32_t b0, uint32_t b1) {
    asm volatile("mma.sync.aligned.m16n8k16.row.col.f32.bf16.bf16.f32 "
                 "{%0,%1,%2,%3}, {%4,%5,%6,%7}, {%8,%9}, {%0,%1,%2,%3};"
                 : "+f"(c0), "+f"(c1), "+f"(c2), "+f"(c3)
                 : "r"(a0), "r"(a1), "r"(a2), "r"(a3), "r"(b0), "r"(b1));
}

// LIF step
__device__ __forceinline__ float lif_step(float& mem, float sp, float x) {
    mem = (mem - 0.5f * sp) * 0.25f + x;
    return rintf(fminf(fmaxf(mem, 0.0f), 1.0f));
}

// ---------------------------------------------------------------------------
// Preamble (fused): blocks [0,8192) build_bias; [8192,9216) split_w; 9216 prep
// ---------------------------------------------------------------------------
__global__ void __launch_bounds__(256) preamble_kernel(
    const float* __restrict__ qg, const float* __restrict__ qv,
    const float* __restrict__ pg, const float* __restrict__ pv,
    const float* __restrict__ wq, const float* __restrict__ wp,
    const float* __restrict__ bias_table) {
    int bb = blockIdx.x;
    int tid = threadIdx.x;
    if (bb < 8192) {
        // build bias block-Toeplitz matrices (bf16 hi/lo)
        int ni = bb & 255, by = bb >> 8;
        int h = by >> 2, dt = by & 3;
        int nj = tid;
        int yi = ni >> 4, xi = ni & 15;
        int yj = nj >> 4, xj = nj & 15;
        int idx = (dt + 3) * 961 + (yi - yj + 15) * 31 + (xi - xj + 15);
        float f = bias_table[idx * NH + h];
        __nv_bfloat16 hi = __float2bfloat16(f);
        __nv_bfloat16 lo = __float2bfloat16(f - __bfloat162float(hi));
        size_t b0 = ((size_t)(((h * 2 + 0) * 4 + dt) * 256 + ni)) * 256 + nj;
        size_t b1 = ((size_t)(((h * 2 + 1) * 4 + dt) * 256 + ni)) * 256 + nj;
        g_bs[b0] = hi;
        g_bs[b1] = lo;
    } else if (bb < 9216) {
        // split weights into 3 bf16 terms
        int i = (bb - 8192) * 256 + tid;
        float v;
        __nv_bfloat16* base;
        int stride, idx;
        if (i < 196608) { v = wq[i]; base = g_ws; stride = 196608; idx = i; }
        else            { idx = i - 196608; v = wp[idx]; base = g_wp; stride = 65536; }
        __nv_bfloat16 h = __float2bfloat16(v);
        float r1 = v - __bfloat162float(h);
        __nv_bfloat16 l = __float2bfloat16(r1);
        float r2 = r1 - __bfloat162float(l);
        base[idx]              = h;
        base[stride + idx]     = l;
        base[2 * stride + idx] = __float2bfloat16(r2);
    } else {
        // BN scales
        for (int o = tid; o < 768; o += 256) {
            float vv = qv[o] + 1e-5f;
            g_scale[o] = qg[o] * (float)(1.0 / sqrt((double)vv));
        }
        {
            int o = tid;
            float vv = pv[o] + 1e-5f;
            g_scale[768 + o] = pg[o] * (float)(1.0 / sqrt((double)vv));
        }
    }
}

// ---------------------------------------------------------------------------
// QKV GEMM (exact R8 structure — known good): in-loop X convert, 2 CTAs/SM.
// grid (8 l-tiles, 6 m-tiles, 8 b), 256 threads = 8 warps (2M x 4N).
// Dynamic SMEM: sA[3][128][40] + sB[3][128][40] bf16 = 61440 B.
// ---------------------------------------------------------------------------
__global__ void __launch_bounds__(256, 2) qkv_gemm(const float* __restrict__ X,
                                                   const float* __restrict__ meanv,
                                                   const float* __restrict__ betav) {
    extern __shared__ __align__(16) char dyn[];
    __nv_bfloat16* sA = (__nv_bfloat16*)dyn;           // [3][128][40]
    __nv_bfloat16* sB = sA + 3 * 128 * 40;             // [3][128][40]

    int tid = threadIdx.x;
    int wid = tid >> 5, lane = tid & 31;
    int l0 = blockIdx.x * 128;
    int m0 = blockIdx.y * 128;
    int b  = blockIdx.z;
    int wm = wid >> 2, wn = wid & 3;

    const float* Xb = X + (size_t)b * (CC * TNTOK);

    float acc[4][4][4];
#pragma unroll
    for (int mt = 0; mt < 4; mt++)
#pragma unroll
        for (int nt = 0; nt < 4; nt++)
#pragma unroll
            for (int q = 0; q < 4; q++) acc[mt][nt][q] = 0.0f;

    int cp = tid >> 4;          // 0..15 -> column pair
    int lr = tid & 15;          // row group for convert

    for (int k0 = 0; k0 < 256; k0 += 32) {
        // A: cp.async 3 splits x 128 rows x 64B
#pragma unroll
        for (int r = 0; r < 6; r++) {
            int idx = tid + r * 256;
            int s = idx >> 9, rem = idx & 511;
            int row = rem >> 2, c16 = rem & 3;
            const __nv_bfloat16* src =
                g_ws + (size_t)s * 196608 + (size_t)(m0 + row) * 256 + k0 + c16 * 8;
            cpasync16(s2u(sA + ((s * 128 + row) * 40 + c16 * 8)), src);
        }
        asm volatile("cp.async.commit_group;" ::: "memory");

        // B: load X fp32, convert to 3 bf16 splits, store transposed [l][k]
        int c0 = k0 + 2 * cp;
#pragma unroll
        for (int r = 0; r < 8; r++) {
            int row = lr + 16 * r;               // l - l0
            int l = l0 + row;
            float v0 = Xb[(size_t)c0 * TNTOK + l];
            float v1 = Xb[(size_t)(c0 + 1) * TNTOK + l];
            __nv_bfloat16 h0 = __float2bfloat16(v0);
            __nv_bfloat16 h1 = __float2bfloat16(v1);
            float r10 = v0 - __bfloat162float(h0);
            float r11 = v1 - __bfloat162float(h1);
            __nv_bfloat16 e0 = __float2bfloat16(r10);
            __nv_bfloat16 e1 = __float2bfloat16(r11);
            float r20 = r10 - __bfloat162float(e0);
            float r21 = r11 - __bfloat162float(e1);
            __nv_bfloat162 ph; ph.x = h0; ph.y = h1;
            __nv_bfloat162 pl; pl.x = e0; pl.y = e1;
            __nv_bfloat162 pq; pq.x = __float2bfloat16(r20); pq.y = __float2bfloat16(r21);
            *(__nv_bfloat162*)(sB + ((0 * 128 + row) * 40 + cp * 2)) = ph;
            *(__nv_bfloat162*)(sB + ((1 * 128 + row) * 40 + cp * 2)) = pl;
            *(__nv_bfloat162*)(sB + ((2 * 128 + row) * 40 + cp * 2)) = pq;
        }
        asm volatile("cp.async.wait_group 0;" ::: "memory");
        __syncthreads();

#pragma unroll
        for (int k16 = 0; k16 < 2; k16++) {
            int kk0 = k16 * 16;
#pragma unroll
            for (int sa = 0; sa < 3; sa++) {
                uint32_t af[4][4];
#pragma unroll
                for (int mt = 0; mt < 4; mt++) {
                    int mrow = wm * 64 + mt * 16 + (lane & 15);
                    int kk = kk0 + ((lane >> 4) << 3);
                    ldsm_x4(af[mt][0], af[mt][1], af[mt][2], af[mt][3],
                            s2u(sA + ((sa * 128 + mrow) * 40 + kk)));
                }
                int nsb = (sa == 0) ? 3 : ((sa == 1) ? 2 : 1);
#pragma unroll
                for (int sb = 0; sb < 3; sb++) {
                    if (sb >= nsb) break;
                    uint32_t bfr[2][4];
#pragma unroll
                    for (int np = 0; np < 2; np++) {
                        int nrow = wn * 32 + np * 16 + (lane & 7) + ((lane >> 4) << 3);
                        int kk = kk0 + (((lane >> 3) & 1) << 3);
                        ldsm_x4(bfr[np][0], bfr[np][1], bfr[np][2], bfr[np][3],
                                s2u(sB + ((sb * 128 + nrow) * 40 + kk)));
                    }
#pragma unroll
                    for (int mt = 0; mt < 4; mt++)
#pragma unroll
                        for (int nt = 0; nt < 4; nt++) {
                            uint32_t b0 = bfr[nt >> 1][(nt & 1) * 2];
                            uint32_t b1 = bfr[nt >> 1][(nt & 1) * 2 + 1];
                            mma_bf16(acc[mt][nt][0], acc[mt][nt][1],
                                     acc[mt][nt][2], acc[mt][nt][3],
                                     af[mt][0], af[mt][1], af[mt][2], af[mt][3], b0, b1);
                        }
                }
            }
        }
        __syncthreads();
    }

    // BN epilogue + store to g_qkv[b][m][l]
    float* Cb = g_qkv + (size_t)b * (768 * TNTOK);
#pragma unroll
    for (int mt = 0; mt < 4; mt++) {
        int row0 = m0 + wm * 64 + mt * 16 + (lane >> 2);
        int row1 = row0 + 8;
        float sc0 = g_scale[row0], mu0 = meanv[row0], be0 = betav[row0];
        float sc1 = g_scale[row1], mu1 = meanv[row1], be1 = betav[row1];
#pragma unroll
        for (int nt = 0; nt < 4; nt++) {
            int col = l0 + wn * 32 + nt * 8 + ((lane & 3) << 1);
            float2 lo2, hi2;
            lo2.x = (acc[mt][nt][0] - mu0) * sc0 + be0;
            lo2.y = (acc[mt][nt][1] - mu0) * sc0 + be0;
            hi2.x = (acc[mt][nt][2] - mu1) * sc1 + be1;
            hi2.y = (acc[mt][nt][3] - mu1) * sc1 + be1;
            *(float2*)(Cb + (size_t)row0 * TNTOK + col) = lo2;
            *(float2*)(Cb + (size_t)row1 * TNTOK + col) = hi2;
        }
    }
}

// ---------------------------------------------------------------------------
// LIF1 + bit-pack + fused V^T bf16 expansion. One block per (g,b), 1024
// threads = (dq 0..3) x (n 0..255); each thread runs 8 channels' LIF, packs
// 8-bit partials, OR-combined via SMEM (no atomics). which==2 also writes g_vt.
// ---------------------------------------------------------------------------
__global__ void __launch_bounds__(1024) lif1_kernel() {
    __shared__ unsigned sp[4][4][256];   // [t][dq][n]

    int g = blockIdx.x;
    int b = blockIdx.y;
    int tid = threadIdx.x;
    int dq = tid >> 8, n = tid & 255;
    int which = g >> 3, h = g & 7;

    const float* src = g_qkv + ((size_t)(b * 768 + g * 32)) * TNTOK + n;
    unsigned w0 = 0, w1 = 0, w2 = 0, w3 = 0;
#pragma unroll
    for (int di = 0; di < 8; di++) {
        int d = dq * 8 + di;
        const float* p = src + (size_t)d * TNTOK;
        float mem = 0.0f, spv = 0.0f;
        float s0 = lif_step(mem, spv, p[0]);   spv = s0;
        float s1 = lif_step(mem, spv, p[256]); spv = s1;
        float s2 = lif_step(mem, spv, p[512]); spv = s2;
        float s3 = lif_step(mem, spv, p[768]);
        w0 |= ((unsigned)s0) << d;
        w1 |= ((unsigned)s1) << d;
        w2 |= ((unsigned)s2) << d;
        w3 |= ((unsigned)s3) << d;
        if (which == 2) {
            // fused build_vt: g_vt[((h*4+tj)*256 + b*32+d)*256 + n]
            size_t vb = ((size_t)((h * 4 + 0) * 256 + b * 32 + d)) * 256 + n;
            g_vt[vb]             = __float2bfloat16(s0);
            g_vt[vb + 1 * 65536] = __float2bfloat16(s1);
            g_vt[vb + 2 * 65536] = __float2bfloat16(s2);
            g_vt[vb + 3 * 65536] = __float2bfloat16(s3);
        }
    }
    sp[0][dq][n] = w0;
    sp[1][dq][n] = w1;
    sp[2][dq][n] = w2;
    sp[3][dq][n] = w3;
    __syncthreads();

    if (dq == 0) {
        unsigned* dst = (which == 0) ? g_qw : ((which == 1) ? g_kw : g_vw);
        size_t base = (size_t)(b * NH + h) * TNTOK + n;
#pragma unroll
        for (int t = 0; t < 4; t++) {
            unsigned w = sp[t][0][n] | sp[t][1][n] | sp[t][2][n] | sp[t][3][n];
            dst[base + t * 256] = w;
        }
    }
}

// ---------------------------------------------------------------------------
// term2 GEMM via mma.sync, 4-stage pipelined (validated R8)
// ---------------------------------------------------------------------------
__global__ void __launch_bounds__(256) term2_gemm() {
    extern __shared__ __align__(16) char t2s[];

    int tid = threadIdx.x;
    int wid = tid >> 5, lane = tid & 31;
    int bx = blockIdx.x;            // ((h*4+ti)*2+mh)*2+nh2
    int nh2 = bx & 1, mh = (bx >> 1) & 1, ti = (bx >> 2) & 3, h = bx >> 4;

    int wm = wid >> 2, wn = wid & 3;
    const int half = (ti + 1) * 8;
    const int niter = half * 2;

    float acc[4][4][4];
#pragma unroll
    for (int mt = 0; mt < 4; mt++)
#pragma unroll
        for (int nt = 0; nt < 4; nt++)
#pragma unroll
            for (int q = 0; q < 4; q++) acc[mt][nt][q] = 0.0f;

    auto tileA = [&](int st) { return (__nv_bfloat16*)(t2s + st * 20480); };
    auto tileB = [&](int st) { return (__nv_bfloat16*)(t2s + st * 20480 + 10240); };

    auto load_chunk = [&](int it, int p) {
        int s = (it >= half) ? 1 : 0;
        int rem = it - s * half;
        int tj = rem >> 3, kc = rem & 7, dt = ti - tj;
        const __nv_bfloat16* Asrc =
            g_bs + ((size_t)(((h * 2 + s) * 4 + dt) * 256 + mh * 128)) * 256 + kc * 32;
        const __nv_bfloat16* Bsrc =
            g_vt + ((size_t)((h * 4 + tj) * 256 + nh2 * 128)) * 256 + kc * 32;
        __nv_bfloat16* dA = tileA(p);
        __nv_bfloat16* dB = tileB(p);
#pragma unroll
        for (int r = 0; r < 2; r++) {
            int ix = tid + r * 256;
            int row = ix >> 2, c16 = ix & 3;
            cpasync16(s2u(dA + row * 40 + c16 * 8), Asrc + (size_t)row * 256 + c16 * 8);
            cpasync16(s2u(dB + row * 40 + c16 * 8), Bsrc + (size_t)row * 256 + c16 * 8);
        }
        asm volatile("cp.async.commit_group;" ::: "memory");
    };

    load_chunk(0, 0);
    load_chunk(1, 1);
    load_chunk(2, 2);

    for (int it = 0; it < niter; ++it) {
        int p = it & 3;
        if (it + 3 < niter) {
            load_chunk(it + 3, (it + 3) & 3);
            asm volatile("cp.async.wait_group 3;" ::: "memory");
        } else {
            int rem = niter - 1 - it;
            if (rem == 2)      asm volatile("cp.async.wait_group 2;" ::: "memory");
            else if (rem == 1) asm volatile("cp.async.wait_group 1;" ::: "memory");
            else               asm volatile("cp.async.wait_group 0;" ::: "memory");
        }
        __syncthreads();

        __nv_bfloat16* cA = tileA(p);
        __nv_bfloat16* cB = tileB(p);
#pragma unroll
        for (int k16 = 0; k16 < 2; k16++) {
            int k0 = k16 * 16;
            uint32_t af[4][4];
#pragma unroll
            for (int mt = 0; mt < 4; mt++) {
                int mrow = wm * 64 + mt * 16 + (lane & 15);
                int kk = k0 + ((lane >> 4) << 3);
                ldsm_x4(af[mt][0], af[mt][1], af[mt][2], af[mt][3],
                        s2u(cA + mrow * 40 + kk));
            }
            uint32_t bfr[2][4];
#pragma unroll
            for (int np = 0; np < 2; np++) {
                int nrow = wn * 32 + np * 16 + (lane & 7) + ((lane >> 4) << 3);
                int kk = k0 + (((lane >> 3) & 1) << 3);
                ldsm_x4(bfr[np][0], bfr[np][1], bfr[np][2], bfr[np][3],
                        s2u(cB + nrow * 40 + kk));
            }
#pragma unroll
            for (int mt = 0; mt < 4; mt++)
#pragma unroll
                for (int nt = 0; nt < 4; nt++) {
                    uint32_t b0 = bfr[nt >> 1][(nt & 1) * 2];
                    uint32_t b1 = bfr[nt >> 1][(nt & 1) * 2 + 1];
                    mma_bf16(acc[mt][nt][0], acc[mt][nt][1], acc[mt][nt][2], acc[mt][nt][3],
                             af[mt][0], af[mt][1], af[mt][2], af[mt][3], b0, b1);
                }
        }
        __syncthreads();
    }

#pragma unroll
    for (int mt = 0; mt < 4; mt++) {
#pragma unroll
        for (int nt = 0; nt < 4; nt++) {
            int row = mh * 128 + wm * 64 + mt * 16 + (lane >> 2);
            int col = nh2 * 128 + wn * 32 + nt * 8 + ((lane & 3) << 1);
            float* pD = g_t2 + ((size_t)((h * 4 + ti) * 256 + row)) * 256 + col;
            float2 lo2 = make_float2(acc[mt][nt][0], acc[mt][nt][1]);
            float2 hi2 = make_float2(acc[mt][nt][2], acc[mt][nt][3]);
            *(float2*)pD = lo2;
            *(float2*)(pD + 8 * 256) = hi2;
        }
    }
}

// ---------------------------------------------------------------------------
// Combine: term1 (exact popc prefix matrix) + term2
// ---------------------------------------------------------------------------
__global__ void __launch_bounds__(256) combine_kernel() {
    __shared__ unsigned sKt[32][32];
    __shared__ unsigned sVt[32][32];
    __shared__ __align__(16) float sM[32][32];

    int ti = blockIdx.x;
    int bh = blockIdx.y;
    int b = bh >> 3, h = bh & 7;
    int tid = threadIdx.x;
    int wid = tid >> 5, ln = tid & 31;
    int nwords = 8 * (ti + 1);

    for (int jg = wid; jg < nwords; jg += 8) {
        unsigned kwv = g_kw[(size_t)bh * TNTOK + jg * 32 + ln];
        unsigned vwv = g_vw[(size_t)bh * TNTOK + jg * 32 + ln];
#pragma unroll
        for (int c = 0; c < 32; c++) {
            unsigned bk = __ballot_sync(0xffffffffu, (kwv >> c) & 1u);
            unsigned bv = __ballot_sync(0xffffffffu, (vwv >> c) & 1u);
            if (ln == c) { sKt[c][jg] = bk; sVt[c][jg] = bv; }
        }
    }
    __syncthreads();

    {
        int c = tid >> 3;
        int d0 = (tid & 7) * 4;
#pragma unroll
        for (int u = 0; u < 4; u++) {
            int d = d0 + u;
            int sum = 0;
            for (int w = 0; w < nwords; w++) sum += __popc(sKt[c][w] & sVt[d][w]);
            sM[c][d] = (float)sum;
        }
    }
    __syncthreads();

    int n = tid;
    unsigned qw = g_qw[(size_t)bh * TNTOK + ti * 256 + n];
    float acc[32];
#pragma unroll
    for (int d = 0; d < 32; d++) acc[d] = 0.0f;
#pragma unroll
    for (int c = 0; c < 32; c++) {
        if ((qw >> c) & 1u) {
#pragma unroll
            for (int q = 0; q < 8; q++) {
                float4 m4 = *(const float4*)&sM[c][q * 4];
                acc[q * 4 + 0] += m4.x;
                acc[q * 4 + 1] += m4.y;
                acc[q * 4 + 2] += m4.z;
                acc[q * 4 + 3] += m4.w;
            }
        }
    }
    const float* t2 = g_t2 + ((size_t)((h * 4 + ti) * 256 + n)) * 256 + b * 32;
    float* outp = g_oat + ((size_t)bh * TNTOK + ti * 256 + n) * DHD;
#pragma unroll
    for (int q = 0; q < 8; q++) {
        float4 t = *(const float4*)(t2 + q * 4);
        float4 o;
        o.x = 0.125f * (acc[q * 4 + 0] + t.x);
        o.y = 0.125f * (acc[q * 4 + 1] + t.y);
        o.z = 0.125f * (acc[q * 4 + 2] + t.z);
        o.w = 0.125f * (acc[q * 4 + 3] + t.w);
        *(float4*)(outp + q * 4) = o;
    }
}

// ---------------------------------------------------------------------------
// LIF2: attention output -> transposed bf16 spikes g_s2t[b][l][c]
// ---------------------------------------------------------------------------
__global__ void __launch_bounds__(256) lif2_kernel() {
    int bh = blockIdx.x;
    int b = bh >> 3, h = bh & 7;
    int tid = threadIdx.x;
    int w = tid >> 5, lane = tid & 31;
    for (int j = 0; j < 32; j++) {
        int n = w * 32 + j;
        const float* base = g_oat + ((size_t)bh * TNTOK + n) * DHD + lane;
        float x0 = base[0];
        float x1 = base[256 * DHD];
        float x2 = base[512 * DHD];
        float x3 = base[768 * DHD];
        float mem = 0.0f, sp = 0.0f;
        float s0 = lif_step(mem, sp, x0); sp = s0;
        float s1 = lif_step(mem, sp, x1); sp = s1;
        float s2v = lif_step(mem, sp, x2); sp = s2v;
        float s3 = lif_step(mem, sp, x3);
        size_t o = ((size_t)b * TNTOK + n) * CC + h * DHD + lane;
        g_s2t[o]            = __float2bfloat16(s0);
        g_s2t[o + 256 * CC] = __float2bfloat16(s1);
        g_s2t[o + 512 * CC] = __float2bfloat16(s2v);
        g_s2t[o + 768 * CC] = __float2bfloat16(s3);
    }
}

// ---------------------------------------------------------------------------
// Proj GEMM: C[b,o,l] = sum_c Wp[o,c]*s2[c,l] (+ b_proj, BN). Spikes exact bf16.
// ---------------------------------------------------------------------------
__global__ void __launch_bounds__(256) proj_gemm(const float* __restrict__ meanv,
                                                 const float* __restrict__ betav,
                                                 const float* __restrict__ addb) {
    __shared__ __align__(16) __nv_bfloat16 sA[3][128][40];
    __shared__ __align__(16) __nv_bfloat16 sB[128][40];

    int tid = threadIdx.x;
    int wid = tid >> 5, lane = tid & 31;
    int l0 = blockIdx.x * 128;
    int m0 = blockIdx.y * 128;
    int b  = blockIdx.z;
    int wm = wid >> 2, wn = wid & 3;

    float acc[4][4][4];
#pragma unroll
    for (int mt = 0; mt < 4; mt++)
#pragma unroll
        for (int nt = 0; nt < 4; nt++)
#pragma unroll
            for (int q = 0; q < 4; q++) acc[mt][nt][q] = 0.0f;

    for (int k0 = 0; k0 < 256; k0 += 32) {
#pragma unroll
        for (int r = 0; r < 6; r++) {
            int idx = tid + r * 256;
            int s = idx >> 9, rem = idx & 511;
            int row = rem >> 2, c16 = rem & 3;
            const __nv_bfloat16* src =
                g_wp + (size_t)s * 65536 + (size_t)(m0 + row) * 256 + k0 + c16 * 8;
            cpasync16(s2u(&sA[s][row][c16 * 8]), src);
        }
#pragma unroll
        for (int r = 0; r < 2; r++) {
            int idx = tid + r * 256;
            int row = idx >> 2, c16 = idx & 3;
            const __nv_bfloat16* src =
                g_s2t + ((size_t)b * TNTOK + l0 + row) * CC + k0 + c16 * 8;
            cpasync16(s2u(&sB[row][c16 * 8]), src);
        }
        asm volatile("cp.async.commit_group;" ::: "memory");
        asm volatile("cp.async.wait_group 0;" ::: "memory");
        __syncthreads();

#pragma unroll
        for (int k16 = 0; k16 < 2; k16++) {
            int kk0 = k16 * 16;
            uint32_t bfr[2][4];
#pragma unroll
            for (int np = 0; np < 2; np++) {
                int nrow = wn * 32 + np * 16 + (lane & 7) + ((lane >> 4) << 3);
                int kk = kk0 + (((lane >> 3) & 1) << 3);
                ldsm_x4(bfr[np][0], bfr[np][1], bfr[np][2], bfr[np][3],
                        s2u(&sB[nrow][kk]));
            }
#pragma unroll
            for (int sa = 0; sa < 3; sa++) {
                uint32_t af[4][4];
#pragma unroll
                for (int mt = 0; mt < 4; mt++) {
                    int mrow = wm * 64 + mt * 16 + (lane & 15);
                    int kk = kk0 + ((lane >> 4) << 3);
                    ldsm_x4(af[mt][0], af[mt][1], af[mt][2], af[mt][3],
                            s2u(&sA[sa][mrow][kk]));
                }
#pragma unroll
                for (int mt = 0; mt < 4; mt++)
#pragma unroll
                    for (int nt = 0; nt < 4; nt++) {
                        uint32_t b0 = bfr[nt >> 1][(nt & 1) * 2];
                        uint32_t b1 = bfr[nt >> 1][(nt & 1) * 2 + 1];
                        mma_bf16(acc[mt][nt][0], acc[mt][nt][1],
                                 acc[mt][nt][2], acc[mt][nt][3],
                                 af[mt][0], af[mt][1], af[mt][2], af[mt][3], b0, b1);
                    }
            }
        }
        __syncthreads();
    }

    float* Cb = g_proj + (size_t)b * (CC * TNTOK);
#pragma unroll
    for (int mt = 0; mt < 4; mt++) {
        int row0 = m0 + wm * 64 + mt * 16 + (lane >> 2);
        int row1 = row0 + 8;
        float sc0 = g_scale[768 + row0], mu0 = meanv[row0], be0 = betav[row0], ab0 = addb[row0];
        float sc1 = g_scale[768 + row1], mu1 = meanv[row1], be1 = betav[row1], ab1 = addb[row1];
#pragma unroll
        for (int nt = 0; nt < 4; nt++) {
            int col = l0 + wn * 32 + nt * 8 + ((lane & 3) << 1);
            float2 lo2, hi2;
            lo2.x = (acc[mt][nt][0] + ab0 - mu0) * sc0 + be0;
            lo2.y = (acc[mt][nt][1] + ab0 - mu0) * sc0 + be0;
            hi2.x = (acc[mt][nt][2] + ab1 - mu1) * sc1 + be1;
            hi2.y = (acc[mt][nt][3] + ab1 - mu1) * sc1 + be1;
            *(float2*)(Cb + (size_t)row0 * TNTOK + col) = lo2;
            *(float2*)(Cb + (size_t)row1 * TNTOK + col) = hi2;
        }
    }
}

// ---------------------------------------------------------------------------
// LIF3: proj output -> final spikes
// ---------------------------------------------------------------------------
__global__ void __launch_bounds__(256) lif3_kernel(float* __restrict__ out) {
    int gid = blockIdx.x * 256 + threadIdx.x;
    const float* p = g_proj + (size_t)(gid >> 8) * TNTOK + (gid & 255);
    float x0 = p[0], x1 = p[256], x2 = p[512], x3 = p[768];
    float mem = 0.0f, sp = 0.0f;
    float s0 = lif_step(mem, sp, x0); sp = s0;
    float s1 = lif_step(mem, sp, x1); sp = s1;
    float s2v = lif_step(mem, sp, x2); sp = s2v;
    float s3 = lif_step(mem, sp, x3);
    out[gid]           = s0;
    out[gid +  524288] = s1;
    out[gid + 1048576] = s2v;
    out[gid + 1572864] = s3;
}

// ---------------------------------------------------------------------------
// Launch
// ---------------------------------------------------------------------------
extern "C" void kernel_launch(void* const* d_in, const int* in_sizes, int n_in,
                              void* d_out, int out_size) {
    const float* x          = (const float*)d_in[0];
    const float* w_qkv      = (const float*)d_in[1];
    const float* qkv_gamma  = (const float*)d_in[2];
    const float* qkv_beta   = (const float*)d_in[3];
    const float* qkv_mean   = (const float*)d_in[4];
    const float* qkv_var    = (const float*)d_in[5];
    const float* bias_table = (const float*)d_in[6];
    const float* w_proj     = (const float*)d_in[7];
    const float* b_proj     = (const float*)d_in[8];
    const float* proj_gamma = (const float*)d_in[9];
    const float* proj_beta  = (const float*)d_in[10];
    const float* proj_mean  = (const float*)d_in[11];
    const float* proj_var   = (const float*)d_in[12];
    float* out = (float*)d_out;

    cudaFuncSetAttribute(qkv_gemm, cudaFuncAttributeMaxDynamicSharedMemorySize, 61440);
    cudaFuncSetAttribute(term2_gemm, cudaFuncAttributeMaxDynamicSharedMemorySize, 81920);

    // Fused preamble: build_bias (8192 blocks) + split_w (1024) + prep (1)
    preamble_kernel<<<9217, 256>>>(qkv_gamma, qkv_var, proj_gamma, proj_var,
                                   w_qkv, w_proj, bias_table);

    qkv_gemm<<<dim3(8, 6, 8), 256, 61440>>>(x, qkv_mean, qkv_beta);

    // LIF1 + bitpack + fused V^T expansion
    lif1_kernel<<<dim3(24, 8), 1024>>>();

    term2_gemm<<<128, 256, 81920>>>();
    combine_kernel<<<dim3(4, 64), 256>>>();

    lif2_kernel<<<64, 256>>>();
    proj_gemm<<<dim3(8, 2, 8), 256>>>(proj_mean, proj_beta, b_proj);
    lif3_kernel<<<2048, 256>>>(out);
}

// round 14
// speedup vs baseline: 1.1542x; 1.0662x over previous
#include <cuda_runtime.h>
#include <cuda_bf16.h>
#include <cstdint>
#include <math.h>

// Problem constants
#define TT 4
#define BB 8
#define CC 256
#define NN 256
#define TNTOK 1024   // T*N
#define NH 8
#define DHD 32

// ---------------------------------------------------------------------------
// Scratch (device globals; no allocation allowed)
// ---------------------------------------------------------------------------
__device__ __align__(16) float    g_qkv [BB * 768 * TNTOK];
__device__ __align__(16) float    g_proj[BB * CC * TNTOK];
__device__ __align__(16) float    g_oat [BB * NH * TNTOK * DHD];
__device__ __align__(16) unsigned g_qw  [BB * NH * TNTOK];
__device__ __align__(16) unsigned g_kw  [BB * NH * TNTOK];
__device__ __align__(16) unsigned g_vw  [BB * NH * TNTOK];
__device__ __align__(16) float    g_scale[1024];
// weight splits (3-term bf16)
__device__ __align__(16) __nv_bfloat16 g_ws[3 * 768 * 256];   // qkv weight splits
__device__ __align__(16) __nv_bfloat16 g_wp[3 * 256 * 256];   // proj weight splits
// transposed bf16 spikes for proj GEMM: [b][l][c]
__device__ __align__(16) __nv_bfloat16 g_s2t[BB * TNTOK * CC];
// attention-restructure buffers
__device__ __align__(16) __nv_bfloat16 g_bs[NH * 2 * 4 * 256 * 256]; // [h][split][dt][ni][nj]
__device__ __align__(16) __nv_bfloat16 g_vt[NH * 4 * 256 * 256];     // [h][tj][col=b*32+d][nj]
__device__ __align__(16) float         g_t2 [NH * 4 * 256 * 256];    // K-half 0 partial
__device__ __align__(16) float         g_t2b[NH * 4 * 256 * 256];    // K-half 1 partial

// ---------------------------------------------------------------------------
// Helpers
// ---------------------------------------------------------------------------
__device__ __forceinline__ uint32_t s2u(const void* p) {
    uint32_t a;
    asm("{ .reg .u64 t; cvta.to.shared.u64 t, %1; cvt.u32.u64 %0, t; }" : "=r"(a) : "l"(p));
    return a;
}
__device__ __forceinline__ void cpasync16(uint32_t dst, const void* src) {
    asm volatile("cp.async.cg.shared.global [%0], [%1], 16;" :: "r"(dst), "l"(src));
}
__device__ __forceinline__ void ldsm_x4(uint32_t& r0, uint32_t& r1, uint32_t& r2, uint32_t& r3,
                                        uint32_t addr) {
    asm volatile("ldmatrix.sync.aligned.m8n8.x4.shared.b16 {%0,%1,%2,%3}, [%4];"
                 : "=r"(r0), "=r"(r1), "=r"(r2), "=r"(r3) : "r"(addr));
}
__device__ __forceinline__ void mma_bf16(float& c0, float& c1, float& c2, float& c3,
                                         uint32_t a0, uint32_t a1, uint32_t a2, uint32_t a3,
                                         uint32_t b0, uint32_t b1) {
    asm volatile("mma.sync.aligned.m16n8k16.row.col.f32.bf16.bf16.f32 "
                 "{%0,%1,%2,%3}, {%4,%5,%6,%7}, {%8,%9}, {%0,%1,%2,%3};"
                 : "+f"(c0), "+f"(c1), "+f"(c2), "+f"(c3)
                 : "r"(a0), "r"(a1), "r"(a2), "r"(a3), "r"(b0), "r"(b1));
}

// LIF step
__device__ __forceinline__ float lif_step(float& mem, float sp, float x) {
    mem = (mem - 0.5f * sp) * 0.25f + x;
    return rintf(fminf(fmaxf(mem, 0.0f), 1.0f));
}

// ---------------------------------------------------------------------------
// Preamble (fused): blocks [0,8192) build_bias; [8192,9216) split_w; 9216 prep
// ---------------------------------------------------------------------------
__global__ void __launch_bounds__(256) preamble_kernel(
    const float* __restrict__ qg, const float* __restrict__ qv,
    const float* __restrict__ pg, const float* __restrict__ pv,
    const float* __restrict__ wq, const float* __restrict__ wp,
    const float* __restrict__ bias_table) {
    int bb = blockIdx.x;
    int tid = threadIdx.x;
    if (bb < 8192) {
        int ni = bb & 255, by = bb >> 8;
        int h = by >> 2, dt = by & 3;
        int nj = tid;
        int yi = ni >> 4, xi = ni & 15;
        int yj = nj >> 4, xj = nj & 15;
        int idx = (dt + 3) * 961 + (yi - yj + 15) * 31 + (xi - xj + 15);
        float f = bias_table[idx * NH + h];
        __nv_bfloat16 hi = __float2bfloat16(f);
        __nv_bfloat16 lo = __float2bfloat16(f - __bfloat162float(hi));
        size_t b0 = ((size_t)(((h * 2 + 0) * 4 + dt) * 256 + ni)) * 256 + nj;
        size_t b1 = ((size_t)(((h * 2 + 1) * 4 + dt) * 256 + ni)) * 256 + nj;
        g_bs[b0] = hi;
        g_bs[b1] = lo;
    } else if (bb < 9216) {
        int i = (bb - 8192) * 256 + tid;
        float v;
        __nv_bfloat16* base;
        int stride, idx;
        if (i < 196608) { v = wq[i]; base = g_ws; stride = 196608; idx = i; }
        else            { idx = i - 196608; v = wp[idx]; base = g_wp; stride = 65536; }
        __nv_bfloat16 h = __float2bfloat16(v);
        float r1 = v - __bfloat162float(h);
        __nv_bfloat16 l = __float2bfloat16(r1);
        float r2 = r1 - __bfloat162float(l);
        base[idx]              = h;
        base[stride + idx]     = l;
        base[2 * stride + idx] = __float2bfloat16(r2);
    } else {
        for (int o = tid; o < 768; o += 256) {
            float vv = qv[o] + 1e-5f;
            g_scale[o] = qg[o] * (float)(1.0 / sqrt((double)vv));
        }
        {
            int o = tid;
            float vv = pv[o] + 1e-5f;
            g_scale[768 + o] = pg[o] * (float)(1.0 / sqrt((double)vv));
        }
    }
}

// ---------------------------------------------------------------------------
// QKV GEMM (exact R8 structure — known good): in-loop X convert, 2 CTAs/SM.
// ---------------------------------------------------------------------------
__global__ void __launch_bounds__(256, 2) qkv_gemm(const float* __restrict__ X,
                                                   const float* __restrict__ meanv,
                                                   const float* __restrict__ betav) {
    extern __shared__ __align__(16) char dyn[];
    __nv_bfloat16* sA = (__nv_bfloat16*)dyn;           // [3][128][40]
    __nv_bfloat16* sB = sA + 3 * 128 * 40;             // [3][128][40]

    int tid = threadIdx.x;
    int wid = tid >> 5, lane = tid & 31;
    int l0 = blockIdx.x * 128;
    int m0 = blockIdx.y * 128;
    int b  = blockIdx.z;
    int wm = wid >> 2, wn = wid & 3;

    const float* Xb = X + (size_t)b * (CC * TNTOK);

    float acc[4][4][4];
#pragma unroll
    for (int mt = 0; mt < 4; mt++)
#pragma unroll
        for (int nt = 0; nt < 4; nt++)
#pragma unroll
            for (int q = 0; q < 4; q++) acc[mt][nt][q] = 0.0f;

    int cp = tid >> 4;
    int lr = tid & 15;

    for (int k0 = 0; k0 < 256; k0 += 32) {
#pragma unroll
        for (int r = 0; r < 6; r++) {
            int idx = tid + r * 256;
            int s = idx >> 9, rem = idx & 511;
            int row = rem >> 2, c16 = rem & 3;
            const __nv_bfloat16* src =
                g_ws + (size_t)s * 196608 + (size_t)(m0 + row) * 256 + k0 + c16 * 8;
            cpasync16(s2u(sA + ((s * 128 + row) * 40 + c16 * 8)), src);
        }
        asm volatile("cp.async.commit_group;" ::: "memory");

        int c0 = k0 + 2 * cp;
#pragma unroll
        for (int r = 0; r < 8; r++) {
            int row = lr + 16 * r;
            int l = l0 + row;
            float v0 = Xb[(size_t)c0 * TNTOK + l];
            float v1 = Xb[(size_t)(c0 + 1) * TNTOK + l];
            __nv_bfloat16 h0 = __float2bfloat16(v0);
            __nv_bfloat16 h1 = __float2bfloat16(v1);
            float r10 = v0 - __bfloat162float(h0);
            float r11 = v1 - __bfloat162float(h1);
            __nv_bfloat16 e0 = __float2bfloat16(r10);
            __nv_bfloat16 e1 = __float2bfloat16(r11);
            float r20 = r10 - __bfloat162float(e0);
            float r21 = r11 - __bfloat162float(e1);
            __nv_bfloat162 ph; ph.x = h0; ph.y = h1;
            __nv_bfloat162 pl; pl.x = e0; pl.y = e1;
            __nv_bfloat162 pq; pq.x = __float2bfloat16(r20); pq.y = __float2bfloat16(r21);
            *(__nv_bfloat162*)(sB + ((0 * 128 + row) * 40 + cp * 2)) = ph;
            *(__nv_bfloat162*)(sB + ((1 * 128 + row) * 40 + cp * 2)) = pl;
            *(__nv_bfloat162*)(sB + ((2 * 128 + row) * 40 + cp * 2)) = pq;
        }
        asm volatile("cp.async.wait_group 0;" ::: "memory");
        __syncthreads();

#pragma unroll
        for (int k16 = 0; k16 < 2; k16++) {
            int kk0 = k16 * 16;
#pragma unroll
            for (int sa = 0; sa < 3; sa++) {
                uint32_t af[4][4];
#pragma unroll
                for (int mt = 0; mt < 4; mt++) {
                    int mrow = wm * 64 + mt * 16 + (lane & 15);
                    int kk = kk0 + ((lane >> 4) << 3);
                    ldsm_x4(af[mt][0], af[mt][1], af[mt][2], af[mt][3],
                            s2u(sA + ((sa * 128 + mrow) * 40 + kk)));
                }
                int nsb = (sa == 0) ? 3 : ((sa == 1) ? 2 : 1);
#pragma unroll
                for (int sb = 0; sb < 3; sb++) {
                    if (sb >= nsb) break;
                    uint32_t bfr[2][4];
#pragma unroll
                    for (int np = 0; np < 2; np++) {
                        int nrow = wn * 32 + np * 16 + (lane & 7) + ((lane >> 4) << 3);
                        int kk = kk0 + (((lane >> 3) & 1) << 3);
                        ldsm_x4(bfr[np][0], bfr[np][1], bfr[np][2], bfr[np][3],
                                s2u(sB + ((sb * 128 + nrow) * 40 + kk)));
                    }
#pragma unroll
                    for (int mt = 0; mt < 4; mt++)
#pragma unroll
                        for (int nt = 0; nt < 4; nt++) {
                            uint32_t b0 = bfr[nt >> 1][(nt & 1) * 2];
                            uint32_t b1 = bfr[nt >> 1][(nt & 1) * 2 + 1];
                            mma_bf16(acc[mt][nt][0], acc[mt][nt][1],
                                     acc[mt][nt][2], acc[mt][nt][3],
                                     af[mt][0], af[mt][1], af[mt][2], af[mt][3], b0, b1);
                        }
                }
            }
        }
        __syncthreads();
    }

    float* Cb = g_qkv + (size_t)b * (768 * TNTOK);
#pragma unroll
    for (int mt = 0; mt < 4; mt++) {
        int row0 = m0 + wm * 64 + mt * 16 + (lane >> 2);
        int row1 = row0 + 8;
        float sc0 = g_scale[row0], mu0 = meanv[row0], be0 = betav[row0];
        float sc1 = g_scale[row1], mu1 = meanv[row1], be1 = betav[row1];
#pragma unroll
        for (int nt = 0; nt < 4; nt++) {
            int col = l0 + wn * 32 + nt * 8 + ((lane & 3) << 1);
            float2 lo2, hi2;
            lo2.x = (acc[mt][nt][0] - mu0) * sc0 + be0;
            lo2.y = (acc[mt][nt][1] - mu0) * sc0 + be0;
            hi2.x = (acc[mt][nt][2] - mu1) * sc1 + be1;
            hi2.y = (acc[mt][nt][3] - mu1) * sc1 + be1;
            *(float2*)(Cb + (size_t)row0 * TNTOK + col) = lo2;
            *(float2*)(Cb + (size_t)row1 * TNTOK + col) = hi2;
        }
    }
}

// ---------------------------------------------------------------------------
// LIF1 + bit-pack + fused V^T bf16 expansion (validated R12)
// ---------------------------------------------------------------------------
__global__ void __launch_bounds__(1024) lif1_kernel() {
    __shared__ unsigned sp[4][4][256];

    int g = blockIdx.x;
    int b = blockIdx.y;
    int tid = threadIdx.x;
    int dq = tid >> 8, n = tid & 255;
    int which = g >> 3, h = g & 7;

    const float* src = g_qkv + ((size_t)(b * 768 + g * 32)) * TNTOK + n;
    unsigned w0 = 0, w1 = 0, w2 = 0, w3 = 0;
#pragma unroll
    for (int di = 0; di < 8; di++) {
        int d = dq * 8 + di;
        const float* p = src + (size_t)d * TNTOK;
        float mem = 0.0f, spv = 0.0f;
        float s0 = lif_step(mem, spv, p[0]);   spv = s0;
        float s1 = lif_step(mem, spv, p[256]); spv = s1;
        float s2 = lif_step(mem, spv, p[512]); spv = s2;
        float s3 = lif_step(mem, spv, p[768]);
        w0 |= ((unsigned)s0) << d;
        w1 |= ((unsigned)s1) << d;
        w2 |= ((unsigned)s2) << d;
        w3 |= ((unsigned)s3) << d;
        if (which == 2) {
            size_t vb = ((size_t)((h * 4 + 0) * 256 + b * 32 + d)) * 256 + n;
            g_vt[vb]             = __float2bfloat16(s0);
            g_vt[vb + 1 * 65536] = __float2bfloat16(s1);
            g_vt[vb + 2 * 65536] = __float2bfloat16(s2);
            g_vt[vb + 3 * 65536] = __float2bfloat16(s3);
        }
    }
    sp[0][dq][n] = w0;
    sp[1][dq][n] = w1;
    sp[2][dq][n] = w2;
    sp[3][dq][n] = w3;
    __syncthreads();

    if (dq == 0) {
        unsigned* dst = (which == 0) ? g_qw : ((which == 1) ? g_kw : g_vw);
        size_t base = (size_t)(b * NH + h) * TNTOK + n;
#pragma unroll
        for (int t = 0; t < 4; t++) {
            unsigned w = sp[t][0][n] | sp[t][1][n] | sp[t][2][n] | sp[t][3][n];
            dst[base + t * 256] = w;
        }
    }
}

// ---------------------------------------------------------------------------
// term2 GEMM: split-K 2-way. bx = tio*64 + h*8 + mh*4 + nh2*2 + kh.
// ti = 3 - tio (heavy tiles first). Each CTA does half of (ti+1)*16 chunks,
// accumulating into g_t2 (kh=0) or g_t2b (kh=1); combine adds the halves.
// 4-stage cp.async pipeline (validated R8). Grid 256.
// ---------------------------------------------------------------------------
__global__ void __launch_bounds__(256) term2_gemm() {
    extern __shared__ __align__(16) char t2s[];

    int tid = threadIdx.x;
    int wid = tid >> 5, lane = tid & 31;
    int bx = blockIdx.x;
    int kh  = bx & 1;
    int nh2 = (bx >> 1) & 1;
    int mh  = (bx >> 2) & 1;
    int h   = (bx >> 3) & 7;
    int tio = bx >> 6;
    int ti  = 3 - tio;

    int wm = wid >> 2, wn = wid & 3;
    const int half = (ti + 1) * 8;          // s-split boundary in chunk ids
    const int half_n = (ti + 1) * 8;        // chunks per K-half ( = niter/2 )
    const int start = kh * half_n;

    float acc[4][4][4];
#pragma unroll
    for (int mt = 0; mt < 4; mt++)
#pragma unroll
        for (int nt = 0; nt < 4; nt++)
#pragma unroll
            for (int q = 0; q < 4; q++) acc[mt][nt][q] = 0.0f;

    auto tileA = [&](int st) { return (__nv_bfloat16*)(t2s + st * 20480); };
    auto tileB = [&](int st) { return (__nv_bfloat16*)(t2s + st * 20480 + 10240); };

    auto load_chunk = [&](int ii, int p) {
        int it = start + ii;
        int s = (it >= half) ? 1 : 0;
        int rem = it - s * half;
        int tj = rem >> 3, kc = rem & 7, dt = ti - tj;
        const __nv_bfloat16* Asrc =
            g_bs + ((size_t)(((h * 2 + s) * 4 + dt) * 256 + mh * 128)) * 256 + kc * 32;
        const __nv_bfloat16* Bsrc =
            g_vt + ((size_t)((h * 4 + tj) * 256 + nh2 * 128)) * 256 + kc * 32;
        __nv_bfloat16* dA = tileA(p);
        __nv_bfloat16* dB = tileB(p);
#pragma unroll
        for (int r = 0; r < 2; r++) {
            int ix = tid + r * 256;
            int row = ix >> 2, c16 = ix & 3;
            cpasync16(s2u(dA + row * 40 + c16 * 8), Asrc + (size_t)row * 256 + c16 * 8);
            cpasync16(s2u(dB + row * 40 + c16 * 8), Bsrc + (size_t)row * 256 + c16 * 8);
        }
        asm volatile("cp.async.commit_group;" ::: "memory");
    };

    load_chunk(0, 0);
    load_chunk(1, 1);
    load_chunk(2, 2);

    for (int ii = 0; ii < half_n; ++ii) {
        int p = ii & 3;
        if (ii + 3 < half_n) {
            load_chunk(ii + 3, (ii + 3) & 3);
            asm volatile("cp.async.wait_group 3;" ::: "memory");
        } else {
            int rem = half_n - 1 - ii;
            if (rem == 2)      asm volatile("cp.async.wait_group 2;" ::: "memory");
            else if (rem == 1) asm volatile("cp.async.wait_group 1;" ::: "memory");
            else               asm volatile("cp.async.wait_group 0;" ::: "memory");
        }
        __syncthreads();

        __nv_bfloat16* cA = tileA(p);
        __nv_bfloat16* cB = tileB(p);
#pragma unroll
        for (int k16 = 0; k16 < 2; k16++) {
            int k0 = k16 * 16;
            uint32_t af[4][4];
#pragma unroll
            for (int mt = 0; mt < 4; mt++) {
                int mrow = wm * 64 + mt * 16 + (lane & 15);
                int kk = k0 + ((lane >> 4) << 3);
                ldsm_x4(af[mt][0], af[mt][1], af[mt][2], af[mt][3],
                        s2u(cA + mrow * 40 + kk));
            }
            uint32_t bfr[2][4];
#pragma unroll
            for (int np = 0; np < 2; np++) {
                int nrow = wn * 32 + np * 16 + (lane & 7) + ((lane >> 4) << 3);
                int kk = k0 + (((lane >> 3) & 1) << 3);
                ldsm_x4(bfr[np][0], bfr[np][1], bfr[np][2], bfr[np][3],
                        s2u(cB + nrow * 40 + kk));
            }
#pragma unroll
            for (int mt = 0; mt < 4; mt++)
#pragma unroll
                for (int nt = 0; nt < 4; nt++) {
                    uint32_t b0 = bfr[nt >> 1][(nt & 1) * 2];
                    uint32_t b1 = bfr[nt >> 1][(nt & 1) * 2 + 1];
                    mma_bf16(acc[mt][nt][0], acc[mt][nt][1], acc[mt][nt][2], acc[mt][nt][3],
                             af[mt][0], af[mt][1], af[mt][2], af[mt][3], b0, b1);
                }
        }
        __syncthreads();
    }

    float* dstbase = (kh == 0) ? g_t2 : g_t2b;
#pragma unroll
    for (int mt = 0; mt < 4; mt++) {
#pragma unroll
        for (int nt = 0; nt < 4; nt++) {
            int row = mh * 128 + wm * 64 + mt * 16 + (lane >> 2);
            int col = nh2 * 128 + wn * 32 + nt * 8 + ((lane & 3) << 1);
            float* pD = dstbase + ((size_t)((h * 4 + ti) * 256 + row)) * 256 + col;
            float2 lo2 = make_float2(acc[mt][nt][0], acc[mt][nt][1]);
            float2 hi2 = make_float2(acc[mt][nt][2], acc[mt][nt][3]);
            *(float2*)pD = lo2;
            *(float2*)(pD + 8 * 256) = hi2;
        }
    }
}

// ---------------------------------------------------------------------------
// Combine: term1 (exact popc prefix matrix) + term2 (sum of K-half partials)
// ---------------------------------------------------------------------------
__global__ void __launch_bounds__(256) combine_kernel() {
    __shared__ unsigned sKt[32][32];
    __shared__ unsigned sVt[32][32];
    __shared__ __align__(16) float sM[32][32];

    int ti = blockIdx.x;
    int bh = blockIdx.y;
    int b = bh >> 3, h = bh & 7;
    int tid = threadIdx.x;
    int wid = tid >> 5, ln = tid & 31;
    int nwords = 8 * (ti + 1);

    for (int jg = wid; jg < nwords; jg += 8) {
        unsigned kwv = g_kw[(size_t)bh * TNTOK + jg * 32 + ln];
        unsigned vwv = g_vw[(size_t)bh * TNTOK + jg * 32 + ln];
#pragma unroll
        for (int c = 0; c < 32; c++) {
            unsigned bk = __ballot_sync(0xffffffffu, (kwv >> c) & 1u);
            unsigned bv = __ballot_sync(0xffffffffu, (vwv >> c) & 1u);
            if (ln == c) { sKt[c][jg] = bk; sVt[c][jg] = bv; }
        }
    }
    __syncthreads();

    {
        int c = tid >> 3;
        int d0 = (tid & 7) * 4;
#pragma unroll
        for (int u = 0; u < 4; u++) {
            int d = d0 + u;
            int sum = 0;
            for (int w = 0; w < nwords; w++) sum += __popc(sKt[c][w] & sVt[d][w]);
            sM[c][d] = (float)sum;
        }
    }
    __syncthreads();

    int n = tid;
    unsigned qw = g_qw[(size_t)bh * TNTOK + ti * 256 + n];
    float acc[32];
#pragma unroll
    for (int d = 0; d < 32; d++) acc[d] = 0.0f;
#pragma unroll
    for (int c = 0; c < 32; c++) {
        if ((qw >> c) & 1u) {
#pragma unroll
            for (int q = 0; q < 8; q++) {
                float4 m4 = *(const float4*)&sM[c][q * 4];
                acc[q * 4 + 0] += m4.x;
                acc[q * 4 + 1] += m4.y;
                acc[q * 4 + 2] += m4.z;
                acc[q * 4 + 3] += m4.w;
            }
        }
    }
    size_t t2off = ((size_t)((h * 4 + ti) * 256 + n)) * 256 + b * 32;
    const float* t2a = g_t2 + t2off;
    const float* t2b = g_t2b + t2off;
    float* outp = g_oat + ((size_t)bh * TNTOK + ti * 256 + n) * DHD;
#pragma unroll
    for (int q = 0; q < 8; q++) {
        float4 ta = *(const float4*)(t2a + q * 4);
        float4 tb = *(const float4*)(t2b + q * 4);
        float4 o;
        o.x = 0.125f * (acc[q * 4 + 0] + (ta.x + tb.x));
        o.y = 0.125f * (acc[q * 4 + 1] + (ta.y + tb.y));
        o.z = 0.125f * (acc[q * 4 + 2] + (ta.z + tb.z));
        o.w = 0.125f * (acc[q * 4 + 3] + (ta.w + tb.w));
        *(float4*)(outp + q * 4) = o;
    }
}

// ---------------------------------------------------------------------------
// LIF2: attention output -> transposed bf16 spikes g_s2t[b][l][c]
// ---------------------------------------------------------------------------
__global__ void __launch_bounds__(256) lif2_kernel() {
    int bh = blockIdx.x;
    int b = bh >> 3, h = bh & 7;
    int tid = threadIdx.x;
    int w = tid >> 5, lane = tid & 31;
    for (int j = 0; j < 32; j++) {
        int n = w * 32 + j;
        const float* base = g_oat + ((size_t)bh * TNTOK + n) * DHD + lane;
        float x0 = base[0];
        float x1 = base[256 * DHD];
        float x2 = base[512 * DHD];
        float x3 = base[768 * DHD];
        float mem = 0.0f, sp = 0.0f;
        float s0 = lif_step(mem, sp, x0); sp = s0;
        float s1 = lif_step(mem, sp, x1); sp = s1;
        float s2v = lif_step(mem, sp, x2); sp = s2v;
        float s3 = lif_step(mem, sp, x3);
        size_t o = ((size_t)b * TNTOK + n) * CC + h * DHD + lane;
        g_s2t[o]            = __float2bfloat16(s0);
        g_s2t[o + 256 * CC] = __float2bfloat16(s1);
        g_s2t[o + 512 * CC] = __float2bfloat16(s2v);
        g_s2t[o + 768 * CC] = __float2bfloat16(s3);
    }
}

// ---------------------------------------------------------------------------
// Proj GEMM: C[b,o,l] = sum_c Wp[o,c]*s2[c,l] (+ b_proj, BN). Spikes exact bf16.
// ---------------------------------------------------------------------------
__global__ void __launch_bounds__(256) proj_gemm(const float* __restrict__ meanv,
                                                 const float* __restrict__ betav,
                                                 const float* __restrict__ addb) {
    __shared__ __align__(16) __nv_bfloat16 sA[3][128][40];
    __shared__ __align__(16) __nv_bfloat16 sB[128][40];

    int tid = threadIdx.x;
    int wid = tid >> 5, lane = tid & 31;
    int l0 = blockIdx.x * 128;
    int m0 = blockIdx.y * 128;
    int b  = blockIdx.z;
    int wm = wid >> 2, wn = wid & 3;

    float acc[4][4][4];
#pragma unroll
    for (int mt = 0; mt < 4; mt++)
#pragma unroll
        for (int nt = 0; nt < 4; nt++)
#pragma unroll
            for (int q = 0; q < 4; q++) acc[mt][nt][q] = 0.0f;

    for (int k0 = 0; k0 < 256; k0 += 32) {
#pragma unroll
        for (int r = 0; r < 6; r++) {
            int idx = tid + r * 256;
            int s = idx >> 9, rem = idx & 511;
            int row = rem >> 2, c16 = rem & 3;
            const __nv_bfloat16* src =
                g_wp + (size_t)s * 65536 + (size_t)(m0 + row) * 256 + k0 + c16 * 8;
            cpasync16(s2u(&sA[s][row][c16 * 8]), src);
        }
#pragma unroll
        for (int r = 0; r < 2; r++) {
            int idx = tid + r * 256;
            int row = idx >> 2, c16 = idx & 3;
            const __nv_bfloat16* src =
                g_s2t + ((size_t)b * TNTOK + l0 + row) * CC + k0 + c16 * 8;
            cpasync16(s2u(&sB[row][c16 * 8]), src);
        }
        asm volatile("cp.async.commit_group;" ::: "memory");
        asm volatile("cp.async.wait_group 0;" ::: "memory");
        __syncthreads();

#pragma unroll
        for (int k16 = 0; k16 < 2; k16++) {
            int kk0 = k16 * 16;
            uint32_t bfr[2][4];
#pragma unroll
            for (int np = 0; np < 2; np++) {
                int nrow = wn * 32 + np * 16 + (lane & 7) + ((lane >> 4) << 3);
                int kk = kk0 + (((lane >> 3) & 1) << 3);
                ldsm_x4(bfr[np][0], bfr[np][1], bfr[np][2], bfr[np][3],
                        s2u(&sB[nrow][kk]));
            }
#pragma unroll
            for (int sa = 0; sa < 3; sa++) {
                uint32_t af[4][4];
#pragma unroll
                for (int mt = 0; mt < 4; mt++) {
                    int mrow = wm * 64 + mt * 16 + (lane & 15);
                    int kk = kk0 + ((lane >> 4) << 3);
                    ldsm_x4(af[mt][0], af[mt][1], af[mt][2], af[mt][3],
                            s2u(&sA[sa][mrow][kk]));
                }
#pragma unroll
                for (int mt = 0; mt < 4; mt++)
#pragma unroll
                    for (int nt = 0; nt < 4; nt++) {
                        uint32_t b0 = bfr[nt >> 1][(nt & 1) * 2];
                        uint32_t b1 = bfr[nt >> 1][(nt & 1) * 2 + 1];
                        mma_bf16(acc[mt][nt][0], acc[mt][nt][1],
                                 acc[mt][nt][2], acc[mt][nt][3],
                                 af[mt][0], af[mt][1], af[mt][2], af[mt][3], b0, b1);
                    }
            }
        }
        __syncthreads();
    }

    float* Cb = g_proj + (size_t)b * (CC * TNTOK);
#pragma unroll
    for (int mt = 0; mt < 4; mt++) {
        int row0 = m0 + wm * 64 + mt * 16 + (lane >> 2);
        int row1 = row0 + 8;
        float sc0 = g_scale[768 + row0], mu0 = meanv[row0], be0 = betav[row0], ab0 = addb[row0];
        float sc1 = g_scale[768 + row1], mu1 = meanv[row1], be1 = betav[row1], ab1 = addb[row1];
#pragma unroll
        for (int nt = 0; nt < 4; nt++) {
            int col = l0 + wn * 32 + nt * 8 + ((lane & 3) << 1);
            float2 lo2, hi2;
            lo2.x = (acc[mt][nt][0] + ab0 - mu0) * sc0 + be0;
            lo2.y = (acc[mt][nt][1] + ab0 - mu0) * sc0 + be0;
            hi2.x = (acc[mt][nt][2] + ab1 - mu1) * sc1 + be1;
            hi2.y = (acc[mt][nt][3] + ab1 - mu1) * sc1 + be1;
            *(float2*)(Cb + (size_t)row0 * TNTOK + col) = lo2;
            *(float2*)(Cb + (size_t)row1 * TNTOK + col) = hi2;
        }
    }
}

// ---------------------------------------------------------------------------
// LIF3: proj output -> final spikes
// ---------------------------------------------------------------------------
__global__ void __launch_bounds__(256) lif3_kernel(float* __restrict__ out) {
    int gid = blockIdx.x * 256 + threadIdx.x;
    const float* p = g_proj + (size_t)(gid >> 8) * TNTOK + (gid & 255);
    float x0 = p[0], x1 = p[256], x2 = p[512], x3 = p[768];
    float mem = 0.0f, sp = 0.0f;
    float s0 = lif_step(mem, sp, x0); sp = s0;
    float s1 = lif_step(mem, sp, x1); sp = s1;
    float s2v = lif_step(mem, sp, x2); sp = s2v;
    float s3 = lif_step(mem, sp, x3);
    out[gid]           = s0;
    out[gid +  524288] = s1;
    out[gid + 1048576] = s2v;
    out[gid + 1572864] = s3;
}

// ---------------------------------------------------------------------------
// Launch
// ---------------------------------------------------------------------------
extern "C" void kernel_launch(void* const* d_in, const int* in_sizes, int n_in,
                              void* d_out, int out_size) {
    const float* x          = (const float*)d_in[0];
    const float* w_qkv      = (const float*)d_in[1];
    const float* qkv_gamma  = (const float*)d_in[2];
    const float* qkv_beta   = (const float*)d_in[3];
    const float* qkv_mean   = (const float*)d_in[4];
    const float* qkv_var    = (const float*)d_in[5];
    const float* bias_table = (const float*)d_in[6];
    const float* w_proj     = (const float*)d_in[7];
    const float* b_proj     = (const float*)d_in[8];
    const float* proj_gamma = (const float*)d_in[9];
    const float* proj_beta  = (const float*)d_in[10];
    const float* proj_mean  = (const float*)d_in[11];
    const float* proj_var   = (const float*)d_in[12];
    float* out = (float*)d_out;

    cudaFuncSetAttribute(qkv_gemm, cudaFuncAttributeMaxDynamicSharedMemorySize, 61440);
    cudaFuncSetAttribute(term2_gemm, cudaFuncAttributeMaxDynamicSharedMemorySize, 81920);

    preamble_kernel<<<9217, 256>>>(qkv_gamma, qkv_var, proj_gamma, proj_var,
                                   w_qkv, w_proj, bias_table);

    qkv_gemm<<<dim3(8, 6, 8), 256, 61440>>>(x, qkv_mean, qkv_beta);

    lif1_kernel<<<dim3(24, 8), 1024>>>();

    term2_gemm<<<256, 256, 81920>>>();
    combine_kernel<<<dim3(4, 64), 256>>>();

    lif2_kernel<<<64, 256>>>();
    proj_gemm<<<dim3(8, 2, 8), 256>>>(proj_mean, proj_beta, b_proj);
    lif3_kernel<<<2048, 256>>>(out);
}